// round 1
// baseline (speedup 1.0000x reference)
#include <cuda_runtime.h>
#include <math.h>

// Problem constants
#define EPSV 1e-5f
constexpr int B     = 8;
constexpr int C     = 512;
constexpr int NH    = 8;
constexpr int KD    = 32;    // KEY_DIM
constexpr int HD    = 64;    // HEAD_DIM
constexpr int HQKV  = 1024;  // DIM + NH*KD*2
constexpr int NPIX  = 1600;  // 40*40
constexpr int IH    = 40;
constexpr int IW    = 40;
constexpr float SCALE = 0.17677669529663687f; // 32^-0.5

// Scratch (device globals — allocation-free)
__device__ __align__(16) float g_qkv[(size_t)B * HQKV * NPIX];  // 52.4 MB
__device__ __align__(16) float g_att[(size_t)B * C * NPIX];     // 26.2 MB
__device__ __align__(16) float g_y  [(size_t)B * C * NPIX];     // 26.2 MB

// ---------------------------------------------------------------------------
// GEMM + fused BatchNorm:  out[b][m][n] = BN( sum_k W[m][k] * X[b][k][n] )
// Block tile 64(m) x 64(n), K-chunk 32, 256 threads, 4x4 per-thread microtile.
// ---------------------------------------------------------------------------
__global__ __launch_bounds__(256) void gemm_bn_kernel(
    const float* __restrict__ W, const float* __restrict__ X,
    const float* __restrict__ gamma, const float* __restrict__ beta,
    const float* __restrict__ mean,  const float* __restrict__ var,
    float* __restrict__ out, int M, int K)
{
    __shared__ float sA[64][32];   // W tile [m][k]  (natural layout, broadcast reads)
    __shared__ float sB[32][64];   // X tile [k][n]

    const int tid = threadIdx.x;
    const int tx = tid & 15, ty = tid >> 4;
    const int n0 = blockIdx.x * 64;
    const int m0 = blockIdx.y * 64;
    const int b  = blockIdx.z;
    const float* Xb = X + (size_t)b * K * NPIX;

    float acc[4][4] = {};

    for (int k0 = 0; k0 < K; k0 += 32) {
        #pragma unroll
        for (int l = tid; l < 64 * 32; l += 256) {
            int i = l >> 5, kk = l & 31;
            sA[i][kk] = W[(size_t)(m0 + i) * K + k0 + kk];
        }
        #pragma unroll
        for (int l = tid; l < 32 * 64; l += 256) {
            int kk = l >> 6, j = l & 63;
            sB[kk][j] = Xb[(size_t)(k0 + kk) * NPIX + n0 + j];
        }
        __syncthreads();

        #pragma unroll
        for (int kk = 0; kk < 32; kk += 4) {
            float4 b0 = *(const float4*)&sB[kk + 0][tx * 4];
            float4 b1 = *(const float4*)&sB[kk + 1][tx * 4];
            float4 b2 = *(const float4*)&sB[kk + 2][tx * 4];
            float4 b3 = *(const float4*)&sB[kk + 3][tx * 4];
            #pragma unroll
            for (int ii = 0; ii < 4; ii++) {
                float4 a = *(const float4*)&sA[ty * 4 + ii][kk];
                acc[ii][0] += a.x * b0.x + a.y * b1.x + a.z * b2.x + a.w * b3.x;
                acc[ii][1] += a.x * b0.y + a.y * b1.y + a.z * b2.y + a.w * b3.y;
                acc[ii][2] += a.x * b0.z + a.y * b1.z + a.z * b2.z + a.w * b3.z;
                acc[ii][3] += a.x * b0.w + a.y * b1.w + a.z * b2.w + a.w * b3.w;
            }
        }
        __syncthreads();
    }

    #pragma unroll
    for (int ii = 0; ii < 4; ii++) {
        int m = m0 + ty * 4 + ii;
        float inv = gamma[m] * rsqrtf(var[m] + EPSV);
        float add = beta[m] - mean[m] * inv;
        float4 o;
        o.x = acc[ii][0] * inv + add;
        o.y = acc[ii][1] * inv + add;
        o.z = acc[ii][2] * inv + add;
        o.w = acc[ii][3] * inv + add;
        *(float4*)&out[((size_t)b * M + m) * NPIX + n0 + tx * 4] = o;
    }
}

// ---------------------------------------------------------------------------
// Flash-style attention per (b, head): online softmax, no NxN scratch.
// Block handles 64 query positions; streams K/V in 64-wide tiles through smem.
// Thread grid 16x16; thread owns 4 query rows (i = 4*ty+..) and 4 cols
// (keys j = 4*tx+.. for logits, dims d = 4*tx+.. for the output).
// ---------------------------------------------------------------------------
__global__ __launch_bounds__(256) void attn_kernel()
{
    extern __shared__ float smem[];
    float* sQ = smem;                 // [32][64] (pre-scaled by SCALE)
    float* sK = sQ + 32 * 64;         // [32][64]
    float* sV = sK + 32 * 64;         // [64][68] pad=4: 2-way max conflict, f4-aligned
    float* sP = sV + 64 * 68;         // [64][64]

    const int tid = threadIdx.x;
    const int tx = tid & 15, ty = tid >> 4;
    const int bh = blockIdx.y;                    // b*NH + h
    const int n0 = blockIdx.x * 64;

    const float* qp = g_qkv + (size_t)bh * (2 * KD + HD) * NPIX;
    const float* kp = qp + (size_t)KD * NPIX;
    const float* vp = qp + (size_t)2 * KD * NPIX;

    for (int l = tid; l < KD * 64; l += 256) {
        int c = l >> 6, i = l & 63;
        sQ[c * 64 + i] = qp[(size_t)c * NPIX + n0 + i] * SCALE;
    }

    float m_i[4], l_i[4], acc[4][4];
    #pragma unroll
    for (int ii = 0; ii < 4; ii++) {
        m_i[ii] = -1e30f; l_i[ii] = 0.f;
        #pragma unroll
        for (int jj = 0; jj < 4; jj++) acc[ii][jj] = 0.f;
    }

    for (int m0 = 0; m0 < NPIX; m0 += 64) {
        __syncthreads();   // prior-iter consumers of sK/sV/sP done (also covers sQ load)
        for (int l = tid; l < KD * 64; l += 256) {
            int c = l >> 6, j = l & 63;
            sK[c * 64 + j] = kp[(size_t)c * NPIX + m0 + j];
        }
        for (int l = tid; l < HD * 64; l += 256) {
            int d = l >> 6, j = l & 63;
            sV[d * 68 + j] = vp[(size_t)d * NPIX + m0 + j];
        }
        __syncthreads();

        // S = (scale*Q)^T K  -> s[ii][jj] for queries 4ty+ii, keys 4tx+jj
        float s[4][4] = {};
        #pragma unroll
        for (int c = 0; c < KD; c++) {
            float4 q = *(const float4*)&sQ[c * 64 + ty * 4];
            float4 k = *(const float4*)&sK[c * 64 + tx * 4];
            s[0][0] += q.x * k.x; s[0][1] += q.x * k.y; s[0][2] += q.x * k.z; s[0][3] += q.x * k.w;
            s[1][0] += q.y * k.x; s[1][1] += q.y * k.y; s[1][2] += q.y * k.z; s[1][3] += q.y * k.w;
            s[2][0] += q.z * k.x; s[2][1] += q.z * k.y; s[2][2] += q.z * k.z; s[2][3] += q.z * k.w;
            s[3][0] += q.w * k.x; s[3][1] += q.w * k.y; s[3][2] += q.w * k.z; s[3][3] += q.w * k.w;
        }

        // Online softmax. Row reduction over the 16-lane tx group (xor 1,2,4,8
        // stays inside lanes [0..15]/[16..31] since lane = (ty&1)*16 + tx).
        #pragma unroll
        for (int ii = 0; ii < 4; ii++) {
            float r = fmaxf(fmaxf(s[ii][0], s[ii][1]), fmaxf(s[ii][2], s[ii][3]));
            r = fmaxf(r, __shfl_xor_sync(0xffffffffu, r, 1));
            r = fmaxf(r, __shfl_xor_sync(0xffffffffu, r, 2));
            r = fmaxf(r, __shfl_xor_sync(0xffffffffu, r, 4));
            r = fmaxf(r, __shfl_xor_sync(0xffffffffu, r, 8));
            float mnew  = fmaxf(m_i[ii], r);
            float alpha = __expf(m_i[ii] - mnew);
            m_i[ii] = mnew;
            float p0 = __expf(s[ii][0] - mnew);
            float p1 = __expf(s[ii][1] - mnew);
            float p2 = __expf(s[ii][2] - mnew);
            float p3 = __expf(s[ii][3] - mnew);
            float rs = p0 + p1 + p2 + p3;
            rs += __shfl_xor_sync(0xffffffffu, rs, 1);
            rs += __shfl_xor_sync(0xffffffffu, rs, 2);
            rs += __shfl_xor_sync(0xffffffffu, rs, 4);
            rs += __shfl_xor_sync(0xffffffffu, rs, 8);
            l_i[ii] = l_i[ii] * alpha + rs;
            acc[ii][0] *= alpha; acc[ii][1] *= alpha;
            acc[ii][2] *= alpha; acc[ii][3] *= alpha;
            *(float4*)&sP[(ty * 4 + ii) * 64 + tx * 4] = make_float4(p0, p1, p2, p3);
        }
        __syncthreads();

        // acc[i][d] += sum_j P[i][j] * V[d][j]
        #pragma unroll
        for (int j = 0; j < 64; j += 4) {
            float4 v0 = *(const float4*)&sV[(tx * 4 + 0) * 68 + j];
            float4 v1 = *(const float4*)&sV[(tx * 4 + 1) * 68 + j];
            float4 v2 = *(const float4*)&sV[(tx * 4 + 2) * 68 + j];
            float4 v3 = *(const float4*)&sV[(tx * 4 + 3) * 68 + j];
            #pragma unroll
            for (int ii = 0; ii < 4; ii++) {
                float4 p = *(const float4*)&sP[(ty * 4 + ii) * 64 + j];
                acc[ii][0] += p.x * v0.x + p.y * v0.y + p.z * v0.z + p.w * v0.w;
                acc[ii][1] += p.x * v1.x + p.y * v1.y + p.z * v1.z + p.w * v1.w;
                acc[ii][2] += p.x * v2.x + p.y * v2.y + p.z * v2.z + p.w * v2.w;
                acc[ii][3] += p.x * v3.x + p.y * v3.y + p.z * v3.z + p.w * v3.w;
            }
        }
    }

    float rl[4];
    #pragma unroll
    for (int ii = 0; ii < 4; ii++) rl[ii] = 1.f / l_i[ii];

    const int b = bh >> 3, h = bh & 7;
    #pragma unroll
    for (int jj = 0; jj < 4; jj++) {
        int d = tx * 4 + jj;
        float4 o = make_float4(acc[0][jj] * rl[0], acc[1][jj] * rl[1],
                               acc[2][jj] * rl[2], acc[3][jj] * rl[3]);
        *(float4*)&g_att[((size_t)b * C + h * HD + d) * NPIX + n0 + ty * 4] = o;
    }
}

// ---------------------------------------------------------------------------
// PE branch: depthwise 3x3 conv (SAME) on V reshaped to (B, 512, 40, 40),
// BN, then add attention output:  g_y = BN(dwconv(v)) + g_att
// One block per (b, c) image.
// ---------------------------------------------------------------------------
__global__ __launch_bounds__(256) void pe_kernel(
    const float* __restrict__ pw,
    const float* __restrict__ gamma, const float* __restrict__ beta,
    const float* __restrict__ mean,  const float* __restrict__ var)
{
    __shared__ float img[NPIX];
    const int bc = blockIdx.x;
    const int b = bc >> 9;
    const int c = bc & 511;
    const int h = c >> 6, d = c & 63;
    const float* v = g_qkv + ((size_t)(b * NH + h) * (2 * KD + HD) + 2 * KD + d) * NPIX;
    const int tid = threadIdx.x;

    for (int l = tid; l < NPIX; l += 256) img[l] = v[l];

    float w[9];
    #pragma unroll
    for (int k = 0; k < 9; k++) w[k] = pw[c * 9 + k];
    float inv = gamma[c] * rsqrtf(var[c] + EPSV);
    float add = beta[c] - mean[c] * inv;
    __syncthreads();

    for (int l = tid; l < NPIX; l += 256) {
        int py = l / IW, px = l % IW;
        float s = 0.f;
        #pragma unroll
        for (int ky = 0; ky < 3; ky++) {
            int yy = py + ky - 1;
            if (yy < 0 || yy >= IH) continue;
            #pragma unroll
            for (int kx = 0; kx < 3; kx++) {
                int xx = px + kx - 1;
                if (xx < 0 || xx >= IW) continue;
                s += w[ky * 3 + kx] * img[yy * IW + xx];
            }
        }
        size_t idx = (size_t)bc * NPIX + l;
        g_y[idx] = s * inv + add + g_att[idx];
    }
}

// ---------------------------------------------------------------------------
extern "C" void kernel_launch(void* const* d_in, const int* in_sizes, int n_in,
                              void* d_out, int out_size)
{
    const float* x      = (const float*)d_in[0];
    const float* qkv_w  = (const float*)d_in[1];
    const float* qkv_g  = (const float*)d_in[2];
    const float* qkv_b  = (const float*)d_in[3];
    const float* qkv_m  = (const float*)d_in[4];
    const float* qkv_v  = (const float*)d_in[5];
    const float* pe_w   = (const float*)d_in[6];
    const float* pe_g   = (const float*)d_in[7];
    const float* pe_b   = (const float*)d_in[8];
    const float* pe_m   = (const float*)d_in[9];
    const float* pe_v   = (const float*)d_in[10];
    const float* proj_w = (const float*)d_in[11];
    const float* proj_g = (const float*)d_in[12];
    const float* proj_b = (const float*)d_in[13];
    const float* proj_m = (const float*)d_in[14];
    const float* proj_v = (const float*)d_in[15];
    float* out = (float*)d_out;

    float *qkv_buf, *y_buf;
    cudaGetSymbolAddress((void**)&qkv_buf, g_qkv);
    cudaGetSymbolAddress((void**)&y_buf, g_y);

    const int smem_attn = (32 * 64 + 32 * 64 + 64 * 68 + 64 * 64) * (int)sizeof(float); // 50176
    cudaFuncSetAttribute(attn_kernel, cudaFuncAttributeMaxDynamicSharedMemorySize, smem_attn);

    // 1) qkv = BN(conv1x1(x, qkv_w))
    gemm_bn_kernel<<<dim3(NPIX / 64, HQKV / 64, B), 256>>>(
        qkv_w, x, qkv_g, qkv_b, qkv_m, qkv_v, qkv_buf, HQKV, C);

    // 2) fused flash attention -> g_att
    attn_kernel<<<dim3(NPIX / 64, B * NH), 256, smem_attn>>>();

    // 3) g_y = BN(dwconv3x3(v)) + g_att
    pe_kernel<<<B * C, 256>>>(pe_w, pe_g, pe_b, pe_m, pe_v);

    // 4) out = BN(conv1x1(g_y, proj_w))
    gemm_bn_kernel<<<dim3(NPIX / 64, C / 64, B), 256>>>(
        proj_w, y_buf, proj_g, proj_b, proj_m, proj_v, out, C, C);
}

// round 3
// speedup vs baseline: 2.2407x; 2.2407x over previous
#include <cuda_runtime.h>
#include <cuda_bf16.h>
#include <cstdint>
#include <math.h>

#define EPSV 1e-5f
constexpr int B     = 8;
constexpr int C     = 512;
constexpr int NH    = 8;
constexpr int KD    = 32;
constexpr int HD    = 64;
constexpr int HQKV  = 1024;
constexpr int NPIX  = 1600;
constexpr int IH    = 40;
constexpr int IW    = 40;
constexpr float SCALE = 0.17677669529663687f;

__device__ __align__(16) float g_qkv[(size_t)B * HQKV * NPIX];
__device__ __align__(16) float g_att[(size_t)B * C * NPIX];
__device__ __align__(16) float g_y  [(size_t)B * C * NPIX];

// ===================== helpers =====================
__device__ __forceinline__ float bf_round(float x) {
    return __bfloat162float(__float2bfloat16_rn(x));
}
// pack two floats to bf16x2: result.lo = lo, result.hi = hi
__device__ __forceinline__ uint32_t pack2(float hi, float lo) {
    uint32_t r;
    asm("cvt.rn.bf16x2.f32 %0, %1, %2;" : "=r"(r) : "f"(hi), "f"(lo));
    return r;
}
__device__ __forceinline__ void mma16816(float* c, const uint32_t* a, uint32_t b0, uint32_t b1) {
    asm volatile(
        "mma.sync.aligned.m16n8k16.row.col.f32.bf16.bf16.f32 "
        "{%0,%1,%2,%3}, {%4,%5,%6,%7}, {%8,%9}, {%0,%1,%2,%3};"
        : "+f"(c[0]), "+f"(c[1]), "+f"(c[2]), "+f"(c[3])
        : "r"(a[0]), "r"(a[1]), "r"(a[2]), "r"(a[3]), "r"(b0), "r"(b1));
}

// ============ FlashAttention-2 style HMMA attention (split-bf16) ============
// CTA: 256 threads = 8 warps. 128 queries per CTA, warp w owns rows 16w..16w+15.
// Key tiles of 64 streamed through smem (hi/lo bf16). Max-free softmax.
//
// smem (bytes):
//  QH 0..9216      [128 q][36 c] bf16   (stride 36 for bank spread)
//  QL 9216..18432
//  KH 18432..23040 [64 key][36 c] bf16
//  KL 23040..27648
//  VH 27648..36864 [64 d][72 key] bf16  (stride 72)
//  VL 36864..46080
//  sO (epilogue alias at 0): [64 d][132 q] f32 = 33792
constexpr int SQH = 0, SQL = 9216, SKH = 18432, SKL = 23040, SVH = 27648, SVL = 36864;

__global__ __launch_bounds__(256) void attn_hmma_kernel()
{
    __shared__ __align__(16) char sm[46080];
    __nv_bfloat16* qh = (__nv_bfloat16*)(sm + SQH);
    __nv_bfloat16* ql = (__nv_bfloat16*)(sm + SQL);
    __nv_bfloat16* kh = (__nv_bfloat16*)(sm + SKH);
    __nv_bfloat16* kl = (__nv_bfloat16*)(sm + SKL);
    __nv_bfloat16* vh = (__nv_bfloat16*)(sm + SVH);
    __nv_bfloat16* vl = (__nv_bfloat16*)(sm + SVL);
    float* sO = (float*)sm;   // epilogue alias

    const int tid  = threadIdx.x;
    const int wid  = tid >> 5;
    const int lane = tid & 31;
    const int g    = lane >> 2;      // group id (row within fragment)
    const int tig  = lane & 3;       // thread-in-group
    const int bh   = blockIdx.y;
    const int n0   = blockIdx.x * 128;

    const float* qp = g_qkv + (size_t)bh * 128 * NPIX;
    const float* kp = qp + (size_t)KD * NPIX;
    const float* vp = qp + (size_t)2 * KD * NPIX;

    // ---- stage Q (scaled, hi/lo split) into smem ----
    for (int idx = tid; idx < 128 * 32; idx += 256) {
        int c = idx >> 7, q = idx & 127;
        int n = n0 + q; if (n > NPIX - 1) n = NPIX - 1;
        float v = qp[(size_t)c * NPIX + n] * SCALE;
        float h = bf_round(v);
        qh[q * 36 + c] = __float2bfloat16_rn(h);
        ql[q * 36 + c] = __float2bfloat16_rn(v - h);
    }
    __syncthreads();

    // ---- load Q fragments (persistent) ----
    uint32_t aQh[2][4], aQl[2][4];
    {
        int r0 = wid * 16 + g;
        #pragma unroll
        for (int ks = 0; ks < 2; ks++) {
            int cb = ks * 16 + 2 * tig;
            aQh[ks][0] = *(const uint32_t*)&qh[r0 * 36 + cb];
            aQh[ks][1] = *(const uint32_t*)&qh[(r0 + 8) * 36 + cb];
            aQh[ks][2] = *(const uint32_t*)&qh[r0 * 36 + cb + 8];
            aQh[ks][3] = *(const uint32_t*)&qh[(r0 + 8) * 36 + cb + 8];
            aQl[ks][0] = *(const uint32_t*)&ql[r0 * 36 + cb];
            aQl[ks][1] = *(const uint32_t*)&ql[(r0 + 8) * 36 + cb];
            aQl[ks][2] = *(const uint32_t*)&ql[r0 * 36 + cb + 8];
            aQl[ks][3] = *(const uint32_t*)&ql[(r0 + 8) * 36 + cb + 8];
        }
    }

    float o[8][4];
    #pragma unroll
    for (int i = 0; i < 8; i++)
        #pragma unroll
        for (int j = 0; j < 4; j++) o[i][j] = 0.f;
    float rsum0 = 0.f, rsum1 = 0.f;

    for (int t = 0; t < 25; t++) {
        const int m0 = t * 64;
        __syncthreads();
        // K tile: [64 key][32 c], coalesced gmem reads
        for (int idx = tid; idx < 64 * 32; idx += 256) {
            int c = idx >> 6, k = idx & 63;
            float v = kp[(size_t)c * NPIX + m0 + k];
            float h = bf_round(v);
            kh[k * 36 + c] = __float2bfloat16_rn(h);
            kl[k * 36 + c] = __float2bfloat16_rn(v - h);
        }
        // V tile: [64 d][64 key]
        for (int idx = tid; idx < 64 * 64; idx += 256) {
            int d = idx >> 6, k = idx & 63;
            float v = vp[(size_t)d * NPIX + m0 + k];
            float h = bf_round(v);
            vh[d * 72 + k] = __float2bfloat16_rn(h);
            vl[d * 72 + k] = __float2bfloat16_rn(v - h);
        }
        __syncthreads();

        // ---- S = Q^T K (3-term split), S[nt] is 16x8 keys ----
        float s[8][4];
        #pragma unroll
        for (int nt = 0; nt < 8; nt++) {
            s[nt][0] = s[nt][1] = s[nt][2] = s[nt][3] = 0.f;
            #pragma unroll
            for (int ks = 0; ks < 2; ks++) {
                int key = nt * 8 + g;
                int cb  = ks * 16 + 2 * tig;
                uint32_t bh0 = *(const uint32_t*)&kh[key * 36 + cb];
                uint32_t bh1 = *(const uint32_t*)&kh[key * 36 + cb + 8];
                uint32_t bl0 = *(const uint32_t*)&kl[key * 36 + cb];
                uint32_t bl1 = *(const uint32_t*)&kl[key * 36 + cb + 8];
                mma16816(s[nt], aQh[ks], bh0, bh1);
                mma16816(s[nt], aQh[ks], bl0, bl1);
                mma16816(s[nt], aQl[ks], bh0, bh1);
            }
        }

        // ---- P = exp(S), row sums ----
        #pragma unroll
        for (int nt = 0; nt < 8; nt++) {
            s[nt][0] = __expf(s[nt][0]);
            s[nt][1] = __expf(s[nt][1]);
            s[nt][2] = __expf(s[nt][2]);
            s[nt][3] = __expf(s[nt][3]);
            rsum0 += s[nt][0] + s[nt][1];
            rsum1 += s[nt][2] + s[nt][3];
        }

        // ---- O += P V (3-term split). A-frags built from S registers. ----
        #pragma unroll
        for (int ks = 0; ks < 4; ks++) {
            const int ta = 2 * ks, tb_ = 2 * ks + 1;
            uint32_t ah[4], al[4];
            {
                float p0 = s[ta][0],  p1 = s[ta][1];
                float h0 = bf_round(p0), h1 = bf_round(p1);
                ah[0] = pack2(h1, h0); al[0] = pack2(p1 - h1, p0 - h0);
                p0 = s[ta][2]; p1 = s[ta][3];
                h0 = bf_round(p0); h1 = bf_round(p1);
                ah[1] = pack2(h1, h0); al[1] = pack2(p1 - h1, p0 - h0);
                p0 = s[tb_][0]; p1 = s[tb_][1];
                h0 = bf_round(p0); h1 = bf_round(p1);
                ah[2] = pack2(h1, h0); al[2] = pack2(p1 - h1, p0 - h0);
                p0 = s[tb_][2]; p1 = s[tb_][3];
                h0 = bf_round(p0); h1 = bf_round(p1);
                ah[3] = pack2(h1, h0); al[3] = pack2(p1 - h1, p0 - h0);
            }
            #pragma unroll
            for (int nt = 0; nt < 8; nt++) {
                int d  = nt * 8 + g;
                int kb = ks * 16 + 2 * tig;
                uint32_t bh0 = *(const uint32_t*)&vh[d * 72 + kb];
                uint32_t bh1 = *(const uint32_t*)&vh[d * 72 + kb + 8];
                uint32_t bl0 = *(const uint32_t*)&vl[d * 72 + kb];
                uint32_t bl1 = *(const uint32_t*)&vl[d * 72 + kb + 8];
                mma16816(o[nt], ah, bh0, bh1);
                mma16816(o[nt], ah, bl0, bl1);
                mma16816(o[nt], al, bh0, bh1);
            }
        }
    }

    // ---- reduce row sums across the quad (lanes tig 0..3 share rows) ----
    rsum0 += __shfl_xor_sync(0xffffffffu, rsum0, 1);
    rsum0 += __shfl_xor_sync(0xffffffffu, rsum0, 2);
    rsum1 += __shfl_xor_sync(0xffffffffu, rsum1, 1);
    rsum1 += __shfl_xor_sync(0xffffffffu, rsum1, 2);
    const float inv0 = 1.f / rsum0, inv1 = 1.f / rsum1;

    // ---- epilogue: transpose O through smem (stride 132: conflict-free) ----
    __syncthreads();
    #pragma unroll
    for (int nt = 0; nt < 8; nt++) {
        int d = nt * 8 + 2 * tig;
        int q = wid * 16 + g;
        sO[d * 132 + q]           = o[nt][0] * inv0;
        sO[(d + 1) * 132 + q]     = o[nt][1] * inv0;
        sO[d * 132 + q + 8]       = o[nt][2] * inv1;
        sO[(d + 1) * 132 + q + 8] = o[nt][3] * inv1;
    }
    __syncthreads();

    const int b = bh >> 3, h = bh & 7;
    float* dst = g_att + ((size_t)b * C + h * 64) * NPIX;
    for (int idx = tid; idx < 64 * 128; idx += 256) {
        int d = idx >> 7, q = idx & 127;
        int n = n0 + q;
        if (n < NPIX) dst[(size_t)d * NPIX + n] = sO[d * 132 + q];
    }
}

// ======================= SIMT GEMM + BN (unchanged) =========================
__global__ __launch_bounds__(256) void gemm_bn_kernel(
    const float* __restrict__ W, const float* __restrict__ X,
    const float* __restrict__ gamma, const float* __restrict__ beta,
    const float* __restrict__ mean,  const float* __restrict__ var,
    float* __restrict__ out, int M, int K)
{
    __shared__ float sA[64][32];
    __shared__ float sB[32][64];

    const int tid = threadIdx.x;
    const int tx = tid & 15, ty = tid >> 4;
    const int n0 = blockIdx.x * 64;
    const int m0 = blockIdx.y * 64;
    const int b  = blockIdx.z;
    const float* Xb = X + (size_t)b * K * NPIX;

    float acc[4][4] = {};

    for (int k0 = 0; k0 < K; k0 += 32) {
        #pragma unroll
        for (int l = tid; l < 64 * 32; l += 256) {
            int i = l >> 5, kk = l & 31;
            sA[i][kk] = W[(size_t)(m0 + i) * K + k0 + kk];
        }
        #pragma unroll
        for (int l = tid; l < 32 * 64; l += 256) {
            int kk = l >> 6, j = l & 63;
            sB[kk][j] = Xb[(size_t)(k0 + kk) * NPIX + n0 + j];
        }
        __syncthreads();

        #pragma unroll
        for (int kk = 0; kk < 32; kk += 4) {
            float4 b0 = *(const float4*)&sB[kk + 0][tx * 4];
            float4 b1 = *(const float4*)&sB[kk + 1][tx * 4];
            float4 b2 = *(const float4*)&sB[kk + 2][tx * 4];
            float4 b3 = *(const float4*)&sB[kk + 3][tx * 4];
            #pragma unroll
            for (int ii = 0; ii < 4; ii++) {
                float4 a = *(const float4*)&sA[ty * 4 + ii][kk];
                acc[ii][0] += a.x * b0.x + a.y * b1.x + a.z * b2.x + a.w * b3.x;
                acc[ii][1] += a.x * b0.y + a.y * b1.y + a.z * b2.y + a.w * b3.y;
                acc[ii][2] += a.x * b0.z + a.y * b1.z + a.z * b2.z + a.w * b3.z;
                acc[ii][3] += a.x * b0.w + a.y * b1.w + a.z * b2.w + a.w * b3.w;
            }
        }
        __syncthreads();
    }

    #pragma unroll
    for (int ii = 0; ii < 4; ii++) {
        int m = m0 + ty * 4 + ii;
        float inv = gamma[m] * rsqrtf(var[m] + EPSV);
        float add = beta[m] - mean[m] * inv;
        float4 o;
        o.x = acc[ii][0] * inv + add;
        o.y = acc[ii][1] * inv + add;
        o.z = acc[ii][2] * inv + add;
        o.w = acc[ii][3] * inv + add;
        *(float4*)&out[((size_t)b * M + m) * NPIX + n0 + tx * 4] = o;
    }
}

// ======================= PE branch (unchanged) ==============================
__global__ __launch_bounds__(256) void pe_kernel(
    const float* __restrict__ pw,
    const float* __restrict__ gamma, const float* __restrict__ beta,
    const float* __restrict__ mean,  const float* __restrict__ var)
{
    __shared__ float img[NPIX];
    const int bc = blockIdx.x;
    const int b = bc >> 9;
    const int c = bc & 511;
    const int h = c >> 6, d = c & 63;
    const float* v = g_qkv + ((size_t)(b * NH + h) * (2 * KD + HD) + 2 * KD + d) * NPIX;
    const int tid = threadIdx.x;

    for (int l = tid; l < NPIX; l += 256) img[l] = v[l];

    float w[9];
    #pragma unroll
    for (int k = 0; k < 9; k++) w[k] = pw[c * 9 + k];
    float inv = gamma[c] * rsqrtf(var[c] + EPSV);
    float add = beta[c] - mean[c] * inv;
    __syncthreads();

    for (int l = tid; l < NPIX; l += 256) {
        int py = l / IW, px = l % IW;
        float s = 0.f;
        #pragma unroll
        for (int ky = 0; ky < 3; ky++) {
            int yy = py + ky - 1;
            if (yy < 0 || yy >= IH) continue;
            #pragma unroll
            for (int kx = 0; kx < 3; kx++) {
                int xx = px + kx - 1;
                if (xx < 0 || xx >= IW) continue;
                s += w[ky * 3 + kx] * img[yy * IW + xx];
            }
        }
        size_t idx = (size_t)bc * NPIX + l;
        g_y[idx] = s * inv + add + g_att[idx];
    }
}

// ============================================================================
extern "C" void kernel_launch(void* const* d_in, const int* in_sizes, int n_in,
                              void* d_out, int out_size)
{
    const float* x      = (const float*)d_in[0];
    const float* qkv_w  = (const float*)d_in[1];
    const float* qkv_g  = (const float*)d_in[2];
    const float* qkv_b  = (const float*)d_in[3];
    const float* qkv_m  = (const float*)d_in[4];
    const float* qkv_v  = (const float*)d_in[5];
    const float* pe_w   = (const float*)d_in[6];
    const float* pe_g   = (const float*)d_in[7];
    const float* pe_b   = (const float*)d_in[8];
    const float* pe_m   = (const float*)d_in[9];
    const float* pe_v   = (const float*)d_in[10];
    const float* proj_w = (const float*)d_in[11];
    const float* proj_g = (const float*)d_in[12];
    const float* proj_b = (const float*)d_in[13];
    const float* proj_m = (const float*)d_in[14];
    const float* proj_v = (const float*)d_in[15];
    float* out = (float*)d_out;

    float *qkv_buf, *y_buf;
    cudaGetSymbolAddress((void**)&qkv_buf, g_qkv);
    cudaGetSymbolAddress((void**)&y_buf, g_y);

    // 1) qkv = BN(conv1x1(x, qkv_w))
    gemm_bn_kernel<<<dim3(NPIX / 64, HQKV / 64, B), 256>>>(
        qkv_w, x, qkv_g, qkv_b, qkv_m, qkv_v, qkv_buf, HQKV, C);

    // 2) HMMA flash attention -> g_att   (13 query tiles x 64 (b,h))
    attn_hmma_kernel<<<dim3(13, B * NH), 256>>>();

    // 3) g_y = BN(dwconv3x3(v)) + g_att
    pe_kernel<<<B * C, 256>>>(pe_w, pe_g, pe_b, pe_m, pe_v);

    // 4) out = BN(conv1x1(g_y, proj_w))
    gemm_bn_kernel<<<dim3(NPIX / 64, C / 64, B), 256>>>(
        proj_w, y_buf, proj_g, proj_b, proj_m, proj_v, out, C, C);
}

// round 4
// speedup vs baseline: 2.9367x; 1.3106x over previous
#include <cuda_runtime.h>
#include <cuda_bf16.h>
#include <cstdint>
#include <math.h>

#define EPSV 1e-5f
constexpr int B     = 8;
constexpr int C     = 512;
constexpr int NH    = 8;
constexpr int KD    = 32;
constexpr int HD    = 64;
constexpr int HQKV  = 1024;
constexpr int NPIX  = 1600;
constexpr int IH    = 40;
constexpr int IW    = 40;
constexpr float SCALE = 0.17677669529663687f;

__device__ __align__(16) float g_qkv[(size_t)B * HQKV * NPIX];
__device__ __align__(16) float g_att[(size_t)B * C * NPIX];
__device__ __align__(16) float g_y  [(size_t)B * C * NPIX];

// ===================== helpers =====================
__device__ __forceinline__ float bf_round(float x) {
    return __bfloat162float(__float2bfloat16_rn(x));
}
__device__ __forceinline__ uint32_t pack2(float hi, float lo) {
    uint32_t r;
    asm("cvt.rn.bf16x2.f32 %0, %1, %2;" : "=r"(r) : "f"(hi), "f"(lo));
    return r;
}
__device__ __forceinline__ void mma16816(float* c, const uint32_t* a, uint32_t b0, uint32_t b1) {
    asm volatile(
        "mma.sync.aligned.m16n8k16.row.col.f32.bf16.bf16.f32 "
        "{%0,%1,%2,%3}, {%4,%5,%6,%7}, {%8,%9}, {%0,%1,%2,%3};"
        : "+f"(c[0]), "+f"(c[1]), "+f"(c[2]), "+f"(c[3])
        : "r"(a[0]), "r"(a[1]), "r"(a[2]), "r"(a[3]), "r"(b0), "r"(b1));
}

// ================= HMMA GEMM + BN (split-bf16, 3-term) ======================
// out[b][m][n] = BN(sum_k W[m][k] * X[b][k][n])
// CTA 128(M) x 128(N), 256 thr = 8 warps (4 M x 2 N), warp tile 32x64.
// K streamed in chunks of 32 through smem (hi/lo bf16 split at load).
__global__ __launch_bounds__(256) void gemm_bn_hmma(
    const float* __restrict__ W, const float* __restrict__ X,
    const float* __restrict__ gamma, const float* __restrict__ beta,
    const float* __restrict__ mean,  const float* __restrict__ var,
    float* __restrict__ out, int M, int K)
{
    __shared__ __align__(16) __nv_bfloat16 swh[128 * 36];
    __shared__ __align__(16) __nv_bfloat16 swl[128 * 36];
    __shared__ __align__(16) __nv_bfloat16 sxh[128 * 36];
    __shared__ __align__(16) __nv_bfloat16 sxl[128 * 36];
    __shared__ float sbn[128][2];   // (inv, add) per local m

    const int tid  = threadIdx.x;
    const int wid  = tid >> 5;
    const int lane = tid & 31;
    const int g    = lane >> 2;
    const int tig  = lane & 3;
    const int wm   = wid >> 1;       // 0..3
    const int wn   = wid & 1;        // 0..1
    const int n0   = blockIdx.x * 128;
    const int m0   = blockIdx.y * 128;
    const int b    = blockIdx.z;
    const float* Xb = X + (size_t)b * K * NPIX;

    if (tid < 128) {
        int m = m0 + tid;
        float inv = gamma[m] * rsqrtf(var[m] + EPSV);
        sbn[tid][0] = inv;
        sbn[tid][1] = beta[m] - mean[m] * inv;
    }

    float acc[2][8][4];
    #pragma unroll
    for (int i = 0; i < 2; i++)
        #pragma unroll
        for (int j = 0; j < 8; j++)
            #pragma unroll
            for (int l = 0; l < 4; l++) acc[i][j][l] = 0.f;

    for (int k0 = 0; k0 < K; k0 += 32) {
        __syncthreads();
        // W tile [128 m][32 k] -> smem [m][36] hi/lo
        #pragma unroll
        for (int idx = tid; idx < 128 * 32; idx += 256) {
            int i = idx >> 5, kk = idx & 31;
            float v = W[(size_t)(m0 + i) * K + k0 + kk];
            float h = bf_round(v);
            swh[i * 36 + kk] = __float2bfloat16_rn(h);
            swl[i * 36 + kk] = __float2bfloat16_rn(v - h);
        }
        // X tile [32 k][128 n] -> smem [n][36] hi/lo (transpose on store)
        #pragma unroll
        for (int idx = tid; idx < 32 * 128; idx += 256) {
            int kk = idx >> 7, j = idx & 127;
            int n = n0 + j; if (n > NPIX - 1) n = NPIX - 1;
            float v = Xb[(size_t)(k0 + kk) * NPIX + n];
            float h = bf_round(v);
            sxh[j * 36 + kk] = __float2bfloat16_rn(h);
            sxl[j * 36 + kk] = __float2bfloat16_rn(v - h);
        }
        __syncthreads();

        #pragma unroll
        for (int ks = 0; ks < 2; ks++) {
            const int cb = ks * 16 + 2 * tig;
            uint32_t aWh[2][4], aWl[2][4];
            #pragma unroll
            for (int mf = 0; mf < 2; mf++) {
                int r0 = wm * 32 + mf * 16 + g;
                aWh[mf][0] = *(const uint32_t*)&swh[r0 * 36 + cb];
                aWh[mf][1] = *(const uint32_t*)&swh[(r0 + 8) * 36 + cb];
                aWh[mf][2] = *(const uint32_t*)&swh[r0 * 36 + cb + 8];
                aWh[mf][3] = *(const uint32_t*)&swh[(r0 + 8) * 36 + cb + 8];
                aWl[mf][0] = *(const uint32_t*)&swl[r0 * 36 + cb];
                aWl[mf][1] = *(const uint32_t*)&swl[(r0 + 8) * 36 + cb];
                aWl[mf][2] = *(const uint32_t*)&swl[r0 * 36 + cb + 8];
                aWl[mf][3] = *(const uint32_t*)&swl[(r0 + 8) * 36 + cb + 8];
            }
            #pragma unroll
            for (int nf = 0; nf < 8; nf++) {
                int nr = wn * 64 + nf * 8 + g;
                uint32_t bh0 = *(const uint32_t*)&sxh[nr * 36 + cb];
                uint32_t bh1 = *(const uint32_t*)&sxh[nr * 36 + cb + 8];
                uint32_t bl0 = *(const uint32_t*)&sxl[nr * 36 + cb];
                uint32_t bl1 = *(const uint32_t*)&sxl[nr * 36 + cb + 8];
                #pragma unroll
                for (int mf = 0; mf < 2; mf++) {
                    mma16816(acc[mf][nf], aWh[mf], bh0, bh1);
                    mma16816(acc[mf][nf], aWh[mf], bl0, bl1);
                    mma16816(acc[mf][nf], aWl[mf], bh0, bh1);
                }
            }
        }
    }

    // ---- epilogue: BN + store (float2, predicated on n) ----
    #pragma unroll
    for (int mf = 0; mf < 2; mf++) {
        int mla = wm * 32 + mf * 16 + g;
        int mlb = mla + 8;
        float inva = sbn[mla][0], adda = sbn[mla][1];
        float invb = sbn[mlb][0], addb = sbn[mlb][1];
        float* rowa = out + ((size_t)b * M + m0 + mla) * NPIX;
        float* rowb = out + ((size_t)b * M + m0 + mlb) * NPIX;
        #pragma unroll
        for (int nf = 0; nf < 8; nf++) {
            int n = n0 + wn * 64 + nf * 8 + 2 * tig;
            if (n < NPIX) {
                float2 va = make_float2(acc[mf][nf][0] * inva + adda,
                                        acc[mf][nf][1] * inva + adda);
                float2 vb = make_float2(acc[mf][nf][2] * invb + addb,
                                        acc[mf][nf][3] * invb + addb);
                *(float2*)&rowa[n] = va;
                *(float2*)&rowb[n] = vb;
            }
        }
    }
}

// ============ FlashAttention-2 style HMMA attention (split-bf16) ============
constexpr int SQH = 0, SQL = 9216, SKH = 18432, SKL = 23040, SVH = 27648, SVL = 36864;

__global__ __launch_bounds__(256) void attn_hmma_kernel()
{
    __shared__ __align__(16) char sm[46080];
    __nv_bfloat16* qh = (__nv_bfloat16*)(sm + SQH);
    __nv_bfloat16* ql = (__nv_bfloat16*)(sm + SQL);
    __nv_bfloat16* kh = (__nv_bfloat16*)(sm + SKH);
    __nv_bfloat16* kl = (__nv_bfloat16*)(sm + SKL);
    __nv_bfloat16* vh = (__nv_bfloat16*)(sm + SVH);
    __nv_bfloat16* vl = (__nv_bfloat16*)(sm + SVL);
    float* sO = (float*)sm;

    const int tid  = threadIdx.x;
    const int wid  = tid >> 5;
    const int lane = tid & 31;
    const int g    = lane >> 2;
    const int tig  = lane & 3;
    const int bh   = blockIdx.y;
    const int n0   = blockIdx.x * 128;

    const float* qp = g_qkv + (size_t)bh * 128 * NPIX;
    const float* kp = qp + (size_t)KD * NPIX;
    const float* vp = qp + (size_t)2 * KD * NPIX;

    for (int idx = tid; idx < 128 * 32; idx += 256) {
        int c = idx >> 7, q = idx & 127;
        int n = n0 + q; if (n > NPIX - 1) n = NPIX - 1;
        float v = qp[(size_t)c * NPIX + n] * SCALE;
        float h = bf_round(v);
        qh[q * 36 + c] = __float2bfloat16_rn(h);
        ql[q * 36 + c] = __float2bfloat16_rn(v - h);
    }
    __syncthreads();

    uint32_t aQh[2][4], aQl[2][4];
    {
        int r0 = wid * 16 + g;
        #pragma unroll
        for (int ks = 0; ks < 2; ks++) {
            int cb = ks * 16 + 2 * tig;
            aQh[ks][0] = *(const uint32_t*)&qh[r0 * 36 + cb];
            aQh[ks][1] = *(const uint32_t*)&qh[(r0 + 8) * 36 + cb];
            aQh[ks][2] = *(const uint32_t*)&qh[r0 * 36 + cb + 8];
            aQh[ks][3] = *(const uint32_t*)&qh[(r0 + 8) * 36 + cb + 8];
            aQl[ks][0] = *(const uint32_t*)&ql[r0 * 36 + cb];
            aQl[ks][1] = *(const uint32_t*)&ql[(r0 + 8) * 36 + cb];
            aQl[ks][2] = *(const uint32_t*)&ql[r0 * 36 + cb + 8];
            aQl[ks][3] = *(const uint32_t*)&ql[(r0 + 8) * 36 + cb + 8];
        }
    }

    float o[8][4];
    #pragma unroll
    for (int i = 0; i < 8; i++)
        #pragma unroll
        for (int j = 0; j < 4; j++) o[i][j] = 0.f;
    float rsum0 = 0.f, rsum1 = 0.f;

    for (int t = 0; t < 25; t++) {
        const int m0 = t * 64;
        __syncthreads();
        for (int idx = tid; idx < 64 * 32; idx += 256) {
            int c = idx >> 6, k = idx & 63;
            float v = kp[(size_t)c * NPIX + m0 + k];
            float h = bf_round(v);
            kh[k * 36 + c] = __float2bfloat16_rn(h);
            kl[k * 36 + c] = __float2bfloat16_rn(v - h);
        }
        for (int idx = tid; idx < 64 * 64; idx += 256) {
            int d = idx >> 6, k = idx & 63;
            float v = vp[(size_t)d * NPIX + m0 + k];
            float h = bf_round(v);
            vh[d * 72 + k] = __float2bfloat16_rn(h);
            vl[d * 72 + k] = __float2bfloat16_rn(v - h);
        }
        __syncthreads();

        float s[8][4];
        #pragma unroll
        for (int nt = 0; nt < 8; nt++) {
            s[nt][0] = s[nt][1] = s[nt][2] = s[nt][3] = 0.f;
            #pragma unroll
            for (int ks = 0; ks < 2; ks++) {
                int key = nt * 8 + g;
                int cb  = ks * 16 + 2 * tig;
                uint32_t bh0 = *(const uint32_t*)&kh[key * 36 + cb];
                uint32_t bh1 = *(const uint32_t*)&kh[key * 36 + cb + 8];
                uint32_t bl0 = *(const uint32_t*)&kl[key * 36 + cb];
                uint32_t bl1 = *(const uint32_t*)&kl[key * 36 + cb + 8];
                mma16816(s[nt], aQh[ks], bh0, bh1);
                mma16816(s[nt], aQh[ks], bl0, bl1);
                mma16816(s[nt], aQl[ks], bh0, bh1);
            }
        }

        #pragma unroll
        for (int nt = 0; nt < 8; nt++) {
            s[nt][0] = __expf(s[nt][0]);
            s[nt][1] = __expf(s[nt][1]);
            s[nt][2] = __expf(s[nt][2]);
            s[nt][3] = __expf(s[nt][3]);
            rsum0 += s[nt][0] + s[nt][1];
            rsum1 += s[nt][2] + s[nt][3];
        }

        #pragma unroll
        for (int ks = 0; ks < 4; ks++) {
            const int ta = 2 * ks, tb_ = 2 * ks + 1;
            uint32_t ah[4], al[4];
            {
                float p0 = s[ta][0],  p1 = s[ta][1];
                float h0 = bf_round(p0), h1 = bf_round(p1);
                ah[0] = pack2(h1, h0); al[0] = pack2(p1 - h1, p0 - h0);
                p0 = s[ta][2]; p1 = s[ta][3];
                h0 = bf_round(p0); h1 = bf_round(p1);
                ah[1] = pack2(h1, h0); al[1] = pack2(p1 - h1, p0 - h0);
                p0 = s[tb_][0]; p1 = s[tb_][1];
                h0 = bf_round(p0); h1 = bf_round(p1);
                ah[2] = pack2(h1, h0); al[2] = pack2(p1 - h1, p0 - h0);
                p0 = s[tb_][2]; p1 = s[tb_][3];
                h0 = bf_round(p0); h1 = bf_round(p1);
                ah[3] = pack2(h1, h0); al[3] = pack2(p1 - h1, p0 - h0);
            }
            #pragma unroll
            for (int nt = 0; nt < 8; nt++) {
                int d  = nt * 8 + g;
                int kb = ks * 16 + 2 * tig;
                uint32_t bh0 = *(const uint32_t*)&vh[d * 72 + kb];
                uint32_t bh1 = *(const uint32_t*)&vh[d * 72 + kb + 8];
                uint32_t bl0 = *(const uint32_t*)&vl[d * 72 + kb];
                uint32_t bl1 = *(const uint32_t*)&vl[d * 72 + kb + 8];
                mma16816(o[nt], ah, bh0, bh1);
                mma16816(o[nt], ah, bl0, bl1);
                mma16816(o[nt], al, bh0, bh1);
            }
        }
    }

    rsum0 += __shfl_xor_sync(0xffffffffu, rsum0, 1);
    rsum0 += __shfl_xor_sync(0xffffffffu, rsum0, 2);
    rsum1 += __shfl_xor_sync(0xffffffffu, rsum1, 1);
    rsum1 += __shfl_xor_sync(0xffffffffu, rsum1, 2);
    const float inv0 = 1.f / rsum0, inv1 = 1.f / rsum1;

    __syncthreads();
    #pragma unroll
    for (int nt = 0; nt < 8; nt++) {
        int d = nt * 8 + 2 * tig;
        int q = wid * 16 + g;
        sO[d * 132 + q]           = o[nt][0] * inv0;
        sO[(d + 1) * 132 + q]     = o[nt][1] * inv0;
        sO[d * 132 + q + 8]       = o[nt][2] * inv1;
        sO[(d + 1) * 132 + q + 8] = o[nt][3] * inv1;
    }
    __syncthreads();

    const int b = bh >> 3, h = bh & 7;
    float* dst = g_att + ((size_t)b * C + h * 64) * NPIX;
    for (int idx = tid; idx < 64 * 128; idx += 256) {
        int d = idx >> 7, q = idx & 127;
        int n = n0 + q;
        if (n < NPIX) dst[(size_t)d * NPIX + n] = sO[d * 132 + q];
    }
}

// ======================= PE branch ==============================
__global__ __launch_bounds__(256) void pe_kernel(
    const float* __restrict__ pw,
    const float* __restrict__ gamma, const float* __restrict__ beta,
    const float* __restrict__ mean,  const float* __restrict__ var)
{
    __shared__ float img[NPIX];
    const int bc = blockIdx.x;
    const int b = bc >> 9;
    const int c = bc & 511;
    const int h = c >> 6, d = c & 63;
    const float* v = g_qkv + ((size_t)(b * NH + h) * (2 * KD + HD) + 2 * KD + d) * NPIX;
    const int tid = threadIdx.x;

    for (int l = tid; l < NPIX; l += 256) img[l] = v[l];

    float w[9];
    #pragma unroll
    for (int k = 0; k < 9; k++) w[k] = pw[c * 9 + k];
    float inv = gamma[c] * rsqrtf(var[c] + EPSV);
    float add = beta[c] - mean[c] * inv;
    __syncthreads();

    for (int l = tid; l < NPIX; l += 256) {
        int py = l / IW, px = l % IW;
        float s = 0.f;
        #pragma unroll
        for (int ky = 0; ky < 3; ky++) {
            int yy = py + ky - 1;
            if (yy < 0 || yy >= IH) continue;
            #pragma unroll
            for (int kx = 0; kx < 3; kx++) {
                int xx = px + kx - 1;
                if (xx < 0 || xx >= IW) continue;
                s += w[ky * 3 + kx] * img[yy * IW + xx];
            }
        }
        size_t idx = (size_t)bc * NPIX + l;
        g_y[idx] = s * inv + add + g_att[idx];
    }
}

// ============================================================================
extern "C" void kernel_launch(void* const* d_in, const int* in_sizes, int n_in,
                              void* d_out, int out_size)
{
    const float* x      = (const float*)d_in[0];
    const float* qkv_w  = (const float*)d_in[1];
    const float* qkv_g  = (const float*)d_in[2];
    const float* qkv_b  = (const float*)d_in[3];
    const float* qkv_m  = (const float*)d_in[4];
    const float* qkv_v  = (const float*)d_in[5];
    const float* pe_w   = (const float*)d_in[6];
    const float* pe_g   = (const float*)d_in[7];
    const float* pe_b   = (const float*)d_in[8];
    const float* pe_m   = (const float*)d_in[9];
    const float* pe_v   = (const float*)d_in[10];
    const float* proj_w = (const float*)d_in[11];
    const float* proj_g = (const float*)d_in[12];
    const float* proj_b = (const float*)d_in[13];
    const float* proj_m = (const float*)d_in[14];
    const float* proj_v = (const float*)d_in[15];
    float* out = (float*)d_out;

    float *qkv_buf, *y_buf;
    cudaGetSymbolAddress((void**)&qkv_buf, g_qkv);
    cudaGetSymbolAddress((void**)&y_buf, g_y);

    // 1) qkv = BN(conv1x1(x, qkv_w))  — HMMA split-bf16
    gemm_bn_hmma<<<dim3(13, HQKV / 128, B), 256>>>(
        qkv_w, x, qkv_g, qkv_b, qkv_m, qkv_v, qkv_buf, HQKV, C);

    // 2) HMMA flash attention -> g_att
    attn_hmma_kernel<<<dim3(13, B * NH), 256>>>();

    // 3) g_y = BN(dwconv3x3(v)) + g_att
    pe_kernel<<<B * C, 256>>>(pe_w, pe_g, pe_b, pe_m, pe_v);

    // 4) out = BN(conv1x1(g_y, proj_w)) — HMMA split-bf16
    gemm_bn_hmma<<<dim3(13, C / 128, B), 256>>>(
        proj_w, y_buf, proj_g, proj_b, proj_m, proj_v, out, C, C);
}